// round 5
// baseline (speedup 1.0000x reference)
#include <cuda_runtime.h>
#include <math.h>

// ---------------------------------------------------------------------------
// FCOS3D target assignment — round 5: warp-autonomous, barrier-free.
// Each lane holds 2 of the M=64 GTs in registers (1 coalesced global RT).
// Per-warp point bbox via shuffle reduction; ballot filter; survivors
// broadcast via shfl in increasing-index order (argmin tie-break preserved).
// No shared memory, no __syncthreads.
// ---------------------------------------------------------------------------

#define NLVL 5
#define NPTS 30929
#define INF_ 1.0e8f

__device__ __constant__ int   c_off[NLVL + 1] = {0, 23200, 29000, 30450, 30825, 30929};
__device__ __constant__ int   c_w[NLVL]       = {200, 100, 50, 25, 13};
__device__ __constant__ float c_s[NLVL]       = {8.f, 16.f, 32.f, 64.f, 128.f};
__device__ __constant__ float c_inv_s[NLVL]   = {0.125f, 0.0625f, 0.03125f, 0.015625f, 0.0078125f};
__device__ __constant__ float c_cent_k[NLVL]  = {
    -2.5f / (1.414f * 8.f   * 1.5f),
    -2.5f / (1.414f * 16.f  * 1.5f),
    -2.5f / (1.414f * 32.f  * 1.5f),
    -2.5f / (1.414f * 64.f  * 1.5f),
    -2.5f / (1.414f * 128.f * 1.5f)};
__device__ __constant__ float c_r0[NLVL]      = {-1.f, 48.f, 96.f, 192.f, 384.f};
__device__ __constant__ float c_r1[NLVL]      = {48.f, 96.f, 192.f, 384.f, 1.0e8f};

__global__ void __launch_bounds__(256)
fcos3d_target_kernel(
    const float* __restrict__ gt_bboxes,    // (B, M, 4)
    const float* __restrict__ g3d,          // (B, M, 9)
    const int*   __restrict__ gl3d,         // (B, M)
    const float* __restrict__ centers2d,    // (B, M, 2)
    const float* __restrict__ depths,       // (B, M)
    const int*   __restrict__ attrs,        // (B, M)
    float*       __restrict__ out,
    int M, int B)
{
    const int b    = blockIdx.y;
    const int tid  = threadIdx.x;
    const int lane = tid & 31;

    // ---- per-thread point coords (clamped for warp convergence) ----
    const int n_raw = blockIdx.x * blockDim.x + tid;
    const bool valid = (n_raw < NPTS);
    const int n = valid ? n_raw : (NPTS - 1);

    int lvl = 0;
#pragma unroll
    for (int i = 1; i < NLVL; i++)
        if (n >= c_off[i]) lvl = i;

    const int   p   = n - c_off[lvl];
    const int   w   = c_w[lvl];
    const float s   = c_s[lvl];
    const float x   = (float)(p % w) * s + 0.5f * s;
    const float y   = (float)(p / w) * s + 0.5f * s;
    const float r0  = c_r0[lvl];
    const float r1  = c_r1[lvl];
    const float rad = s * 1.5f;

    // ---- issue this lane's GT loads early (2 GTs/lane for M=64) ----
    const float2* cptr = reinterpret_cast<const float2*>(centers2d) + (size_t)b * M;
    const float4* bptr = reinterpret_cast<const float4*>(gt_bboxes) + (size_t)b * M;
    const int nrounds = (M + 31) >> 5;   // 2 for M=64

    float2 myc[2];
    float4 mybb[2];
#pragma unroll 2
    for (int r = 0; r < nrounds && r < 2; r++) {
        const int m = r * 32 + lane;
        if (m < M) { myc[r] = cptr[m]; mybb[r] = bptr[m]; }
        else       { myc[r] = make_float2(-1e30f, -1e30f); mybb[r] = make_float4(0,0,0,0); }
    }

    // ---- per-warp point bbox via shuffle reduction ----
    float xmn = x, xmx = x, ymn = y, ymx = y, rmx = rad;
#pragma unroll
    for (int o = 16; o > 0; o >>= 1) {
        xmn = fminf(xmn, __shfl_xor_sync(0xffffffffu, xmn, o));
        xmx = fmaxf(xmx, __shfl_xor_sync(0xffffffffu, xmx, o));
        ymn = fminf(ymn, __shfl_xor_sync(0xffffffffu, ymn, o));
        ymx = fmaxf(ymx, __shfl_xor_sync(0xffffffffu, ymx, o));
        rmx = fmaxf(rmx, __shfl_xor_sync(0xffffffffu, rmx, o));
    }
    const float bxmin = xmn - rmx, bxmax = xmx + rmx;
    const float bymin = ymn - rmx, bymax = ymx + rmx;

    // ---- filter + argmin over shuffle-broadcast survivors ----
    float best = INF_;
    int   bi   = 0;     // all-INF argmin -> index 0 (matches reference)
#pragma unroll 2
    for (int r = 0; r < nrounds && r < 2; r++) {
        const float2 c_r  = myc[r];
        const bool ok = (c_r.x >= bxmin) & (c_r.x <= bxmax) &
                        (c_r.y >= bymin) & (c_r.y <= bymax);
        unsigned mask = __ballot_sync(0xffffffffu, ok);
        while (mask) {
            const int src = __ffs(mask) - 1;
            mask &= mask - 1;
            const float cx  = __shfl_sync(0xffffffffu, c_r.x,  src);
            const float cy  = __shfl_sync(0xffffffffu, c_r.y,  src);
            const float b0  = __shfl_sync(0xffffffffu, mybb[r].x, src);
            const float b1  = __shfl_sync(0xffffffffu, mybb[r].y, src);
            const float b2  = __shfl_sync(0xffffffffu, mybb[r].z, src);
            const float b3  = __shfl_sync(0xffffffffu, mybb[r].w, src);

            const float dx = x - cx;
            const float dy = y - cy;
            const float mrd = fmaxf(fmaxf(x - b0, y - b1), fmaxf(b2 - x, b3 - y));
            const bool good = (mrd >= r0) & (mrd <= r1) &
                              (fmaxf(fabsf(dx), fabsf(dy)) < rad);
            const float d2 = good ? fmaf(dx, dx, dy * dy) : INF_;
            if (d2 < best) { best = d2; bi = r * 32 + src; }
        }
    }

    if (!valid) return;

    const bool bg = (best >= INF_);

    // ---- gather the winner's payload (winner indices cluster -> L1 hot) ----
    const int gi = b * M + bi;
    const float2 c = cptr[bi];
    const float dx = x - c.x;
    const float dy = y - c.y;
    const float* g = g3d + (size_t)gi * 9;
    const float yaw = -atan2f(g[0], g[2]) + g[6];

    const float cent = expf(c_cent_k[lvl] * sqrtf(fmaf(dx, dx, dy * dy)));

    const int BN   = B * NPTS;
    const int npl  = c_off[lvl + 1] - c_off[lvl];
    const int base = c_off[lvl] * B + b * npl + p;
    const float inv_s = c_inv_s[lvl];

    out[base]           = bg ? 10.f : (float)gl3d[gi];   // labels_3d
    out[10 * BN + base] = cent;                          // centerness
    out[11 * BN + base] = bg ? 9.f : (float)attrs[gi];   // attr

    float* bo = out + BN + (size_t)base * 9;             // bbox_targets_3d
    bo[0] = dx * inv_s;
    bo[1] = dy * inv_s;
    bo[2] = depths[gi];
    bo[3] = g[3];
    bo[4] = g[4];
    bo[5] = g[5];
    bo[6] = yaw;
    bo[7] = g[7];
    bo[8] = g[8];
}

extern "C" void kernel_launch(void* const* d_in, const int* in_sizes, int n_in,
                              void* d_out, int out_size)
{
    const float* gt_bboxes = (const float*)d_in[0];
    const float* g3d       = (const float*)d_in[2];
    const int*   gl3d      = (const int*)  d_in[3];
    const float* centers2d = (const float*)d_in[4];
    const float* depths    = (const float*)d_in[5];
    const int*   attrs     = (const int*)  d_in[6];
    float* out = (float*)d_out;

    const int B = out_size / (12 * NPTS);
    const int M = in_sizes[1] / B;

    const int threads = 256;
    dim3 grid((NPTS + threads - 1) / threads, B);
    fcos3d_target_kernel<<<grid, threads>>>(
        gt_bboxes, g3d, gl3d, centers2d, depths, attrs, out, M, B);
}

// round 6
// speedup vs baseline: 1.3821x; 1.3821x over previous
#include <cuda_runtime.h>
#include <math.h>

// ---------------------------------------------------------------------------
// FCOS3D target assignment — round 6: R3 skeleton, minimal critical path.
// Warp 0 loads all GT centers+bboxes in ONE coalesced round trip, computes an
// analytic block bbox (no shuffle reduction), ballots + writes compacted
// survivors to smem. Single __syncthreads. All threads scan the (tiny)
// candidate list from smem; winner payload gathered from global in epilogue.
// ---------------------------------------------------------------------------

#define NLVL 5
#define NPTS 30929
#define INF_ 1.0e8f
#define MAXM 128

__device__ __constant__ int   c_off[NLVL + 1] = {0, 23200, 29000, 30450, 30825, 30929};
__device__ __constant__ int   c_w[NLVL]       = {200, 100, 50, 25, 13};
__device__ __constant__ float c_s[NLVL]       = {8.f, 16.f, 32.f, 64.f, 128.f};
__device__ __constant__ float c_inv_s[NLVL]   = {0.125f, 0.0625f, 0.03125f, 0.015625f, 0.0078125f};
__device__ __constant__ float c_cent_k[NLVL]  = {
    -2.5f / (1.414f * 8.f   * 1.5f),
    -2.5f / (1.414f * 16.f  * 1.5f),
    -2.5f / (1.414f * 32.f  * 1.5f),
    -2.5f / (1.414f * 64.f  * 1.5f),
    -2.5f / (1.414f * 128.f * 1.5f)};
__device__ __constant__ float c_r0[NLVL]      = {-1.f, 48.f, 96.f, 192.f, 384.f};
__device__ __constant__ float c_r1[NLVL]      = {48.f, 96.f, 192.f, 384.f, 1.0e8f};

__global__ void __launch_bounds__(128)
fcos3d_target_kernel(
    const float* __restrict__ gt_bboxes,    // (B, M, 4)
    const float* __restrict__ g3d,          // (B, M, 9)
    const int*   __restrict__ gl3d,         // (B, M)
    const float* __restrict__ centers2d,    // (B, M, 2)
    const float* __restrict__ depths,       // (B, M)
    const int*   __restrict__ attrs,        // (B, M)
    float*       __restrict__ out,
    int M, int B)
{
    const int b    = blockIdx.y;
    const int tid  = threadIdx.x;
    const int lane = tid & 31;

    __shared__ float4 s_cbb[MAXM];
    __shared__ float2 s_cc[MAXM];
    __shared__ int    s_cidx[MAXM];
    __shared__ int    s_ncand;

    // ---- per-thread point coords (clamped for convergence) ----
    const int n0    = blockIdx.x * blockDim.x;
    const int n_raw = n0 + tid;
    const bool valid = (n_raw < NPTS);
    const int n = valid ? n_raw : (NPTS - 1);

    int lvl = 0;
#pragma unroll
    for (int i = 1; i < NLVL; i++)
        if (n >= c_off[i]) lvl = i;

    const int   p   = n - c_off[lvl];
    const int   w   = c_w[lvl];
    const float s   = c_s[lvl];
    const float x   = (float)(p % w) * s + 0.5f * s;
    const float y   = (float)(p / w) * s + 0.5f * s;
    const float r0  = c_r0[lvl];
    const float r1  = c_r1[lvl];
    const float rad = s * 1.5f;

    // ---- warp 0: one-RT load of all GT centers+bboxes, analytic bbox,
    //      ballot filter, ordered compaction into smem ----
    if (tid < 32) {
        // Issue ALL loads up front (unconditional -> single round trip).
        const float2* cptr = reinterpret_cast<const float2*>(centers2d) + (size_t)b * M;
        const float4* bptr = reinterpret_cast<const float4*>(gt_bboxes) + (size_t)b * M;
        float2 myc[2];
        float4 mybb[2];
#pragma unroll
        for (int r = 0; r < 2; r++) {
            const int m = r * 32 + lane;
            if (m < M) { myc[r] = cptr[m]; mybb[r] = bptr[m]; }
            else       { myc[r] = make_float2(-2e30f, -2e30f); }
        }

        // Analytic block point-bbox (all lanes compute the same values).
        const int nlast = min(n0 + (int)blockDim.x - 1, NPTS - 1);
        float bxmin = 1e30f, bxmax = -1e30f;
        float bymin = 1e30f, bymax = -1e30f, rmx = 0.f;
#pragma unroll
        for (int l = 0; l < NLVL; l++) {
            const int a = max(n0, c_off[l]);
            const int e = min(nlast, c_off[l + 1] - 1);
            if (a > e) continue;
            const int   pw = c_w[l];
            const float ls = c_s[l];
            const int p0 = a - c_off[l], p1 = e - c_off[l];
            const int row0 = p0 / pw, row1 = p1 / pw;
            const int xlo = (row1 > row0) ? 0 : (p0 % pw);
            const int xhi = (row1 > row0) ? (pw - 1) : (p1 % pw);
            bxmin = fminf(bxmin, (float)xlo * ls + 0.5f * ls);
            bxmax = fmaxf(bxmax, (float)xhi * ls + 0.5f * ls);
            bymin = fminf(bymin, (float)row0 * ls + 0.5f * ls);
            bymax = fmaxf(bymax, (float)row1 * ls + 0.5f * ls);
            rmx   = fmaxf(rmx, 1.5f * ls);
        }
        bxmin -= rmx; bxmax += rmx; bymin -= rmx; bymax += rmx;

        int cnt = 0;
#pragma unroll
        for (int r = 0; r < 2; r++) {
            const int m = r * 32 + lane;
            const bool ok = (m < M) &
                            (myc[r].x >= bxmin) & (myc[r].x <= bxmax) &
                            (myc[r].y >= bymin) & (myc[r].y <= bymax);
            const unsigned mask = __ballot_sync(0xffffffffu, ok);
            if (ok) {
                const int pos = cnt + __popc(mask & ((1u << lane) - 1u));
                s_cbb[pos]  = mybb[r];
                s_cc[pos]   = myc[r];
                s_cidx[pos] = m;
            }
            cnt += __popc(mask);
        }
        if (lane == 0) s_ncand = cnt;
    }
    __syncthreads();

    if (!valid) return;

    // ---- argmin over candidates (squared distance; first-min tie-break) ----
    const int ncand = s_ncand;
    float best = INF_;
    int   bk   = -1;
    for (int k = 0; k < ncand; k++) {
        const float4 bb = s_cbb[k];
        const float2 c  = s_cc[k];
        const float dx = x - c.x;
        const float dy = y - c.y;
        const float mrd = fmaxf(fmaxf(x - bb.x, y - bb.y),
                                fmaxf(bb.z - x, bb.w - y));
        const bool ok = (mrd >= r0) & (mrd <= r1) &
                        (fmaxf(fabsf(dx), fabsf(dy)) < rad);
        const float d2 = ok ? fmaf(dx, dx, dy * dy) : INF_;
        if (d2 < best) { best = d2; bk = k; }
    }

    const bool bg = (best >= INF_);
    const int  bi = (bk >= 0) ? s_cidx[bk] : 0;   // all-INF argmin -> index 0

    // ---- gather the winner's payload (bg-dominated -> L1 broadcast hot) ----
    const int gi = b * M + bi;
    const float2 c = reinterpret_cast<const float2*>(centers2d)[gi];
    const float dx = x - c.x;
    const float dy = y - c.y;
    const float* g = g3d + (size_t)gi * 9;
    const float yaw = -atan2f(g[0], g[2]) + g[6];

    const float cent = expf(c_cent_k[lvl] * sqrtf(fmaf(dx, dx, dy * dy)));

    const int BN   = B * NPTS;
    const int npl  = c_off[lvl + 1] - c_off[lvl];
    const int base = c_off[lvl] * B + b * npl + p;
    const float inv_s = c_inv_s[lvl];

    out[base]           = bg ? 10.f : (float)gl3d[gi];   // labels_3d
    out[10 * BN + base] = cent;                          // centerness
    out[11 * BN + base] = bg ? 9.f : (float)attrs[gi];   // attr

    float* bo = out + BN + (size_t)base * 9;             // bbox_targets_3d
    bo[0] = dx * inv_s;
    bo[1] = dy * inv_s;
    bo[2] = depths[gi];
    bo[3] = g[3];
    bo[4] = g[4];
    bo[5] = g[5];
    bo[6] = yaw;
    bo[7] = g[7];
    bo[8] = g[8];
}

extern "C" void kernel_launch(void* const* d_in, const int* in_sizes, int n_in,
                              void* d_out, int out_size)
{
    const float* gt_bboxes = (const float*)d_in[0];
    const float* g3d       = (const float*)d_in[2];
    const int*   gl3d      = (const int*)  d_in[3];
    const float* centers2d = (const float*)d_in[4];
    const float* depths    = (const float*)d_in[5];
    const int*   attrs     = (const int*)  d_in[6];
    float* out = (float*)d_out;

    const int B = out_size / (12 * NPTS);
    const int M = in_sizes[1] / B;

    const int threads = 128;
    dim3 grid((NPTS + threads - 1) / threads, B);
    fcos3d_target_kernel<<<grid, threads>>>(
        gt_bboxes, g3d, gl3d, centers2d, depths, attrs, out, M, B);
}